// round 2
// baseline (speedup 1.0000x reference)
#include <cuda_runtime.h>
#include <cuda_bf16.h>
#include <math.h>

#define NMAX 50000
#define EMAX 800000

// ---------------- scratch (static device globals; no allocation) -------------
__device__ __align__(16) float    g_h1[NMAX * 128];    // layer1 h = x@W1  [N,2,64]
__device__ __align__(16) float    g_as1[NMAX * 2], g_ad1[NMAX * 2];
__device__ __align__(16) unsigned g_mu1[NMAX * 2];
__device__ __align__(16) float    g_mf1[NMAX * 2], g_den1[NMAX * 2];
__device__ __align__(16) float    g_agg1[NMAX * 128];
__device__ __align__(16) float    g_e1[EMAX * 2];
__device__ __align__(16) float    g_x2[NMAX * 128];    // elu(layer1 out)

__device__ __align__(16) float    g_h2[NMAX * 64];
__device__ __align__(16) float    g_as2[NMAX], g_ad2[NMAX];
__device__ __align__(16) unsigned g_mu2[NMAX];
__device__ __align__(16) float    g_mf2[NMAX], g_den2[NMAX];
__device__ __align__(16) float    g_agg2[NMAX * 64];
__device__ __align__(16) float    g_e2[EMAX];
__device__ __align__(16) float    g_o2[NMAX * 64];     // elu(layer2 out)

// ---------------- helpers ----------------------------------------------------
__device__ __forceinline__ float lrelu02(float x) { return x >= 0.f ? x : 0.2f * x; }
__device__ __forceinline__ unsigned ordf(float f) {
    unsigned u = __float_as_uint(f);
    return (u & 0x80000000u) ? ~u : (u | 0x80000000u);
}
__device__ __forceinline__ float deordf(unsigned u) {
    unsigned b = (u & 0x80000000u) ? (u & 0x7fffffffu) : ~u;
    return __uint_as_float(b);
}
__device__ __forceinline__ void red4(float* p, float4 v) {
    asm volatile("red.global.add.v4.f32 [%0], {%1,%2,%3,%4};"
                 :: "l"(p), "f"(v.x), "f"(v.y), "f"(v.z), "f"(v.w) : "memory");
}

// ---------------- GEMM: H[n,OUT] = X[n,128] @ W[128,OUT] ---------------------
// block = 256 thr (8 warps). One warp per row, 64-col chunk per blockIdx.y.
template <int OUT>
__global__ void gemm_rowwise(const float* __restrict__ X, const float* __restrict__ Wg,
                             float* __restrict__ H, int n) {
    __shared__ float sW[128 * 64];
    __shared__ float sX[8][128];
    const int tid = threadIdx.x, warp = tid >> 5, lane = tid & 31;
    const int colBase = blockIdx.y * 64;
    for (int idx = tid; idx < 128 * 64; idx += 256) {
        int k = idx >> 6, c = idx & 63;
        sW[idx] = Wg[k * OUT + colBase + c];
    }
    __syncthreads();
    for (int r0 = blockIdx.x * 8; r0 < n; r0 += gridDim.x * 8) {
        int row = r0 + warp;
        if (row < n) {
            float4 xv = *(const float4*)&X[(size_t)row * 128 + lane * 4];
            *(float4*)&sX[warp][lane * 4] = xv;
            __syncwarp();
            float2 acc = {0.f, 0.f};
#pragma unroll 16
            for (int k = 0; k < 128; ++k) {
                float x = sX[warp][k];
                float2 w = *(const float2*)&sW[k * 64 + lane * 2];
                acc.x = fmaf(x, w.x, acc.x);
                acc.y = fmaf(x, w.y, acc.y);
            }
            *(float2*)&H[(size_t)row * OUT + colBase + lane * 2] = acc;
            __syncwarp();
        }
    }
}

// ---------------- attention scores -------------------------------------------
// H=2, C=64: warp per node; lane covers 4 cols; head = lane/16.
__global__ void attn_h2(const float* __restrict__ Hm, const float* __restrict__ As,
                        const float* __restrict__ Ad, float* __restrict__ as_,
                        float* __restrict__ ad_, int n) {
    int gw = (blockIdx.x * blockDim.x + threadIdx.x) >> 5;
    int nw = (gridDim.x * blockDim.x) >> 5;
    int lane = threadIdx.x & 31;
    float4 s4 = *(const float4*)&As[lane * 4];
    float4 d4 = *(const float4*)&Ad[lane * 4];
    for (int i = gw; i < n; i += nw) {
        float4 v = *(const float4*)&Hm[(size_t)i * 128 + lane * 4];
        float ps = v.x * s4.x + v.y * s4.y + v.z * s4.z + v.w * s4.w;
        float pd = v.x * d4.x + v.y * d4.y + v.z * d4.z + v.w * d4.w;
#pragma unroll
        for (int o = 8; o; o >>= 1) {
            ps += __shfl_xor_sync(0xffffffffu, ps, o);
            pd += __shfl_xor_sync(0xffffffffu, pd, o);
        }
        if ((lane & 15) == 0) {
            as_[i * 2 + (lane >> 4)] = ps;
            ad_[i * 2 + (lane >> 4)] = pd;
        }
    }
}

// H=1, C=64: warp per node; lane covers 2 cols.
__global__ void attn_h1(const float* __restrict__ Hm, const float* __restrict__ As,
                        const float* __restrict__ Ad, float* __restrict__ as_,
                        float* __restrict__ ad_, int n) {
    int gw = (blockIdx.x * blockDim.x + threadIdx.x) >> 5;
    int nw = (gridDim.x * blockDim.x) >> 5;
    int lane = threadIdx.x & 31;
    float2 s2 = *(const float2*)&As[lane * 2];
    float2 d2 = *(const float2*)&Ad[lane * 2];
    for (int i = gw; i < n; i += nw) {
        float2 v = *(const float2*)&Hm[(size_t)i * 64 + lane * 2];
        float ps = v.x * s2.x + v.y * s2.y;
        float pd = v.x * d2.x + v.y * d2.y;
#pragma unroll
        for (int o = 16; o; o >>= 1) {
            ps += __shfl_xor_sync(0xffffffffu, ps, o);
            pd += __shfl_xor_sync(0xffffffffu, pd, o);
        }
        if (lane == 0) { as_[i] = ps; ad_[i] = pd; }
    }
}

// ---------------- softmax max ------------------------------------------------
__global__ void init_max(const float* __restrict__ as_, const float* __restrict__ ad_,
                         unsigned* __restrict__ mu, int nH) {
    int t = blockIdx.x * blockDim.x + threadIdx.x;
    if (t < nH) mu[t] = ordf(lrelu02(as_[t] + ad_[t]));
}

template <int H>
__global__ void edge_max(const int* __restrict__ src, const int* __restrict__ dst,
                         const float* __restrict__ as_, const float* __restrict__ ad_,
                         float* __restrict__ ebuf, unsigned* __restrict__ mu, int E) {
    int e = blockIdx.x * blockDim.x + threadIdx.x;
    if (e >= E) return;
    int s = src[e], d = dst[e];
#pragma unroll
    for (int h = 0; h < H; ++h) {
        float ev = lrelu02(as_[s * H + h] + ad_[d * H + h]);
        ebuf[(size_t)e * H + h] = ev;
        atomicMax(&mu[d * H + h], ordf(ev));
    }
}

// m -> float, denom init with self-loop weight
__global__ void finalize_max(const float* __restrict__ as_, const float* __restrict__ ad_,
                             const unsigned* __restrict__ mu, float* __restrict__ mf,
                             float* __restrict__ den, int nH) {
    int t = blockIdx.x * blockDim.x + threadIdx.x;
    if (t < nH) {
        float m = deordf(mu[t]);
        mf[t] = m;
        den[t] = expf(lrelu02(as_[t] + ad_[t]) - m);
    }
}

// agg init: agg[i,h,c] = h[i,h,c] * w_self (w_self == den at this point)
template <int H>
__global__ void init_agg(const float* __restrict__ hraw, const float* __restrict__ den,
                         float* __restrict__ agg, int n) {
    const int HC4 = H * 16;  // float4s per node
    int t = blockIdx.x * blockDim.x + threadIdx.x;
    if (t >= n * HC4) return;
    int i = t / HC4;
    int q = t - i * HC4;          // float4 index within node
    int h = (q * 4) >> 6;         // head
    float w0 = den[i * H + h];
    float4 v = ((const float4*)hraw)[t];
    v.x *= w0; v.y *= w0; v.z *= w0; v.w *= w0;
    ((float4*)agg)[t] = v;
}

// ---------------- heavy weighted scatter -------------------------------------
// H=2 (HC=128): one warp per edge, lane covers 4 floats, head = lane/16.
// H=1 (HC=64) : two edges per warp (16 lanes each).
template <int H>
__global__ void edge_sum(const int* __restrict__ src, const int* __restrict__ dst,
                         const float* __restrict__ ebuf, const float* __restrict__ mf,
                         const float* __restrict__ hraw, float* __restrict__ agg,
                         float* __restrict__ den, int E) {
    const int HC = H * 64;
    const int LPE = HC / 4;            // lanes per edge (32 or 16)
    const int EPW = 32 / LPE;          // edges per warp (1 or 2)
    int gw = (blockIdx.x * blockDim.x + threadIdx.x) >> 5;
    int lane = threadIdx.x & 31;
    int sub = lane / LPE;
    int li = lane - sub * LPE;
    int e = gw * EPW + sub;
    if (e >= E) return;
    int s = src[e], d = dst[e];
    int head = (li * 4) >> 6;          // 0 or 1
    float w = expf(ebuf[(size_t)e * H + head] - mf[d * H + head]);
    float4 hv = *(const float4*)&hraw[(size_t)s * HC + li * 4];
    float4 a = {hv.x * w, hv.y * w, hv.z * w, hv.w * w};
    red4(&agg[(size_t)d * HC + li * 4], a);
    if (li == (head << 4)) atomicAdd(&den[d * H + head], w);  // li==0 (and li==16 for H=2)
}

// ---------------- epilogue: divide, bias, elu --------------------------------
template <int H>
__global__ void out_elu(const float* __restrict__ agg, const float* __restrict__ den,
                        const float* __restrict__ bias, float* __restrict__ out, int n) {
    const int HC = H * 64;
    int t = blockIdx.x * blockDim.x + threadIdx.x;
    if (t >= n * HC) return;
    int i = t / HC;
    int hc = t - i * HC;
    int h = hc >> 6;
    float v = agg[t] / (den[i * H + h] + 1e-16f) + bias[hc];
    out[t] = v > 0.f ? v : expm1f(v);
}

// ---------------- final linear + sigmoid -------------------------------------
__global__ void final_lin(const float* __restrict__ H2, const float* __restrict__ Lw,
                          const float* __restrict__ Lb, float* __restrict__ out, int n) {
    __shared__ float sw[64 * 16];
    __shared__ float sb[16];
    int tid = threadIdx.x;
    for (int idx = tid; idx < 64 * 16; idx += 256) sw[idx] = Lw[idx];
    if (tid < 16) sb[tid] = Lb[tid];
    __syncthreads();
    int gw = (blockIdx.x * 256 + tid) >> 5;
    int nw = (gridDim.x * 256) >> 5;
    int lane = tid & 31;
    int o = lane & 15, half = lane >> 4;
    for (int i = gw; i < n; i += nw) {
        const float* row = &H2[(size_t)i * 64 + half * 32];
        float acc = 0.f;
#pragma unroll
        for (int c = 0; c < 32; ++c) acc = fmaf(row[c], sw[(half * 32 + c) * 16 + o], acc);
        acc += __shfl_xor_sync(0xffffffffu, acc, 16);
        if (lane < 16) out[(size_t)i * 16 + o] = 1.f / (1.f + expf(-(acc + sb[o])));
    }
}

// ---------------- launcher ---------------------------------------------------
static inline int cdiv(long long a, long long b) { return (int)((a + b - 1) / b); }

extern "C" void kernel_launch(void* const* d_in, const int* in_sizes, int n_in,
                              void* d_out, int out_size) {
    const float* x   = (const float*)d_in[0];
    const int*   ei  = (const int*)d_in[1];   // int32! (JAX x64 disabled coerces int64->int32)
    const float* W1  = (const float*)d_in[2];
    const float* As1 = (const float*)d_in[3];
    const float* Ad1 = (const float*)d_in[4];
    const float* b1  = (const float*)d_in[5];
    const float* W2  = (const float*)d_in[6];
    const float* As2 = (const float*)d_in[7];
    const float* Ad2 = (const float*)d_in[8];
    const float* b2  = (const float*)d_in[9];
    const float* lw  = (const float*)d_in[10];
    const float* lb  = (const float*)d_in[11];
    float*       out = (float*)d_out;

    int n = in_sizes[0] / 128;
    int E = in_sizes[1] / 2;
    const int* src = ei;
    const int* dst = ei + E;

    float *h1, *as1, *ad1, *mf1, *den1, *agg1, *e1, *x2;
    unsigned* mu1;
    cudaGetSymbolAddress((void**)&h1, g_h1);
    cudaGetSymbolAddress((void**)&as1, g_as1);   cudaGetSymbolAddress((void**)&ad1, g_ad1);
    cudaGetSymbolAddress((void**)&mu1, g_mu1);   cudaGetSymbolAddress((void**)&mf1, g_mf1);
    cudaGetSymbolAddress((void**)&den1, g_den1); cudaGetSymbolAddress((void**)&agg1, g_agg1);
    cudaGetSymbolAddress((void**)&e1, g_e1);     cudaGetSymbolAddress((void**)&x2, g_x2);
    float *h2, *as2, *ad2, *mf2, *den2, *agg2, *e2, *o2;
    unsigned* mu2;
    cudaGetSymbolAddress((void**)&h2, g_h2);
    cudaGetSymbolAddress((void**)&as2, g_as2);   cudaGetSymbolAddress((void**)&ad2, g_ad2);
    cudaGetSymbolAddress((void**)&mu2, g_mu2);   cudaGetSymbolAddress((void**)&mf2, g_mf2);
    cudaGetSymbolAddress((void**)&den2, g_den2); cudaGetSymbolAddress((void**)&agg2, g_agg2);
    cudaGetSymbolAddress((void**)&e2, g_e2);     cudaGetSymbolAddress((void**)&o2, g_o2);

    const int T = 256;

    // ---- layer 1 (H=2, C=64, concat) ----
    gemm_rowwise<128><<<dim3(cdiv(n, 8), 2), T>>>(x, W1, h1, n);
    attn_h2<<<cdiv((long long)n * 32, T), T>>>(h1, As1, Ad1, as1, ad1, n);
    init_max<<<cdiv(n * 2, T), T>>>(as1, ad1, mu1, n * 2);
    edge_max<2><<<cdiv(E, T), T>>>(src, dst, as1, ad1, e1, mu1, E);
    finalize_max<<<cdiv(n * 2, T), T>>>(as1, ad1, mu1, mf1, den1, n * 2);
    init_agg<2><<<cdiv((long long)n * 32, T), T>>>(h1, den1, agg1, n);
    edge_sum<2><<<cdiv((long long)E * 32, T), T>>>(src, dst, e1, mf1, h1, agg1, den1, E);
    out_elu<2><<<cdiv((long long)n * 128, T), T>>>(agg1, den1, b1, x2, n);

    // ---- layer 2 (H=1, C=64, mean over 1 head) ----
    gemm_rowwise<64><<<dim3(cdiv(n, 8), 1), T>>>(x2, W2, h2, n);
    attn_h1<<<cdiv((long long)n * 32, T), T>>>(h2, As2, Ad2, as2, ad2, n);
    init_max<<<cdiv(n, T), T>>>(as2, ad2, mu2, n);
    edge_max<1><<<cdiv(E, T), T>>>(src, dst, as2, ad2, e2, mu2, E);
    finalize_max<<<cdiv(n, T), T>>>(as2, ad2, mu2, mf2, den2, n);
    init_agg<1><<<cdiv((long long)n * 16, T), T>>>(h2, den2, agg2, n);
    edge_sum<1><<<cdiv(((long long)E + 1) / 2 * 32, T), T>>>(src, dst, e2, mf2, h2, agg2, den2, E);
    out_elu<1><<<cdiv((long long)n * 64, T), T>>>(agg2, den2, b2, o2, n);

    // ---- final linear + sigmoid ----
    final_lin<<<cdiv((long long)n * 32, T), T>>>(o2, lw, lb, out, n);
}

// round 7
// speedup vs baseline: 1.5612x; 1.5612x over previous
#include <cuda_runtime.h>
#include <cuda_bf16.h>
#include <math.h>

#define NMAX 50000
#define EMAX 800000

// ---------------- scratch ----------------------------------------------------
__device__ __align__(16) float g_h1[NMAX * 128];
__device__ __align__(16) float g_as1[NMAX * 2], g_ad1[NMAX * 2];
__device__ __align__(16) float g_x2[NMAX * 128];
__device__ __align__(16) float g_h2[NMAX * 64];
__device__ __align__(16) float g_as2[NMAX], g_ad2[NMAX];
__device__ __align__(16) float g_o2[NMAX * 64];
// CSR
__device__ int g_cnt[NMAX];
__device__ int g_rowptr[NMAX + 1];
__device__ int g_woff[NMAX];
__device__ int g_csrc[EMAX];

// ---------------- helpers ----------------------------------------------------
__device__ __forceinline__ float lrelu02(float x) { return x >= 0.f ? x : 0.2f * x; }

// ---------------- CSR build ---------------------------------------------------
__global__ void zero_cnt(int* cnt, int n) {
    int t = blockIdx.x * blockDim.x + threadIdx.x;
    if (t < n) cnt[t] = 0;
}
__global__ void hist_dst(const int* __restrict__ dst, int* __restrict__ cnt, int E) {
    int e = blockIdx.x * blockDim.x + threadIdx.x;
    if (e < E) atomicAdd(&cnt[dst[e]], 1);
}
// single-block exclusive scan (n ~ 50000), writes rowptr[0..n] and woff copy
__global__ void scan_cnt(const int* __restrict__ cnt, int* __restrict__ rowptr,
                         int* __restrict__ woff, int n) {
    __shared__ int warpsum[32];
    __shared__ int s_carry;
    int tid = threadIdx.x, lane = tid & 31, wid = tid >> 5;
    if (tid == 0) s_carry = 0;
    __syncthreads();
    for (int base = 0; base < n; base += 1024) {
        int i = base + tid;
        int v = (i < n) ? cnt[i] : 0;
        int x = v;
#pragma unroll
        for (int o = 1; o < 32; o <<= 1) {
            int y = __shfl_up_sync(0xffffffffu, x, o);
            if (lane >= o) x += y;
        }
        if (lane == 31) warpsum[wid] = x;
        __syncthreads();
        if (wid == 0) {
            int w = warpsum[lane];
#pragma unroll
            for (int o = 1; o < 32; o <<= 1) {
                int y = __shfl_up_sync(0xffffffffu, w, o);
                if (lane >= o) w += y;
            }
            warpsum[lane] = w;
        }
        __syncthreads();
        int pre = (wid > 0 ? warpsum[wid - 1] : 0) + s_carry;
        int excl = pre + x - v;
        if (i < n) { rowptr[i] = excl; woff[i] = excl; }
        __syncthreads();
        if (tid == 1023) s_carry = pre + x;
        __syncthreads();
    }
    if (tid == 0) rowptr[n] = s_carry;
}
__global__ void csr_scatter(const int* __restrict__ src, const int* __restrict__ dst,
                            int* __restrict__ woff, int* __restrict__ csrc, int E) {
    int e = blockIdx.x * blockDim.x + threadIdx.x;
    if (e < E) {
        int d = dst[e];
        int p = atomicAdd(&woff[d], 1);
        csrc[p] = src[e];
    }
}

// ---------------- GEMM: 64x64 tile, 4x4 register blocking --------------------
// H[n,OUT] = X[n,128] @ W[128,OUT].  256 threads, BK=64, two k-tiles.
template <int OUT>
__global__ void gemm64(const float* __restrict__ X, const float* __restrict__ Wg,
                       float* __restrict__ Hout, int n) {
    __shared__ float sA[64][68];   // [k][row], padded
    __shared__ float sB[64][64];   // [k][col]
    const int tid = threadIdx.x;
    const int tx = tid & 15, ty = tid >> 4;
    const int rowBase = blockIdx.x * 64, colBase = blockIdx.y * 64;
    float acc[4][4] = {};
    for (int kt = 0; kt < 2; ++kt) {
        // load A tile: 64 rows x 64 k
        for (int idx = tid; idx < 64 * 16; idx += 256) {
            int r = idx >> 4, kq = idx & 15;
            int row = rowBase + r;
            float4 v = make_float4(0.f, 0.f, 0.f, 0.f);
            if (row < n) v = *(const float4*)&X[(size_t)row * 128 + kt * 64 + kq * 4];
            sA[kq * 4 + 0][r] = v.x; sA[kq * 4 + 1][r] = v.y;
            sA[kq * 4 + 2][r] = v.z; sA[kq * 4 + 3][r] = v.w;
        }
        // load B tile: 64 k x 64 cols
        for (int idx = tid; idx < 64 * 16; idx += 256) {
            int k = idx >> 4, cq = idx & 15;
            *(float4*)&sB[k][cq * 4] =
                *(const float4*)&Wg[(size_t)(kt * 64 + k) * OUT + colBase + cq * 4];
        }
        __syncthreads();
#pragma unroll
        for (int k = 0; k < 64; ++k) {
            float a[4], b[4];
            *(float4*)a = *(const float4*)&sA[k][ty * 4];
            *(float4*)b = *(const float4*)&sB[k][tx * 4];
#pragma unroll
            for (int i = 0; i < 4; ++i)
#pragma unroll
                for (int j = 0; j < 4; ++j)
                    acc[i][j] = fmaf(a[i], b[j], acc[i][j]);
        }
        __syncthreads();
    }
#pragma unroll
    for (int i = 0; i < 4; ++i) {
        int row = rowBase + ty * 4 + i;
        if (row < n)
            *(float4*)&Hout[(size_t)row * OUT + colBase + tx * 4] =
                make_float4(acc[i][0], acc[i][1], acc[i][2], acc[i][3]);
    }
}

// ---------------- attention scores -------------------------------------------
__global__ void attn_h2(const float* __restrict__ Hm, const float* __restrict__ As,
                        const float* __restrict__ Ad, float* __restrict__ as_,
                        float* __restrict__ ad_, int n) {
    int gw = (blockIdx.x * blockDim.x + threadIdx.x) >> 5;
    int nw = (gridDim.x * blockDim.x) >> 5;
    int lane = threadIdx.x & 31;
    float4 s4 = *(const float4*)&As[lane * 4];
    float4 d4 = *(const float4*)&Ad[lane * 4];
    for (int i = gw; i < n; i += nw) {
        float4 v = *(const float4*)&Hm[(size_t)i * 128 + lane * 4];
        float ps = v.x * s4.x + v.y * s4.y + v.z * s4.z + v.w * s4.w;
        float pd = v.x * d4.x + v.y * d4.y + v.z * d4.z + v.w * d4.w;
#pragma unroll
        for (int o = 8; o; o >>= 1) {
            ps += __shfl_xor_sync(0xffffffffu, ps, o);
            pd += __shfl_xor_sync(0xffffffffu, pd, o);
        }
        if ((lane & 15) == 0) {
            as_[i * 2 + (lane >> 4)] = ps;
            ad_[i * 2 + (lane >> 4)] = pd;
        }
    }
}
__global__ void attn_h1(const float* __restrict__ Hm, const float* __restrict__ As,
                        const float* __restrict__ Ad, float* __restrict__ as_,
                        float* __restrict__ ad_, int n) {
    int gw = (blockIdx.x * blockDim.x + threadIdx.x) >> 5;
    int nw = (gridDim.x * blockDim.x) >> 5;
    int lane = threadIdx.x & 31;
    float2 s2 = *(const float2*)&As[lane * 2];
    float2 d2 = *(const float2*)&Ad[lane * 2];
    for (int i = gw; i < n; i += nw) {
        float2 v = *(const float2*)&Hm[(size_t)i * 64 + lane * 2];
        float ps = v.x * s2.x + v.y * s2.y;
        float pd = v.x * d2.x + v.y * d2.y;
#pragma unroll
        for (int o = 16; o; o >>= 1) {
            ps += __shfl_xor_sync(0xffffffffu, ps, o);
            pd += __shfl_xor_sync(0xffffffffu, pd, o);
        }
        if (lane == 0) { as_[i] = ps; ad_[i] = pd; }
    }
}

// ---------------- fused GAT softmax-aggregate (CSR, warp per dst) -------------
// H=2: lanes 0-15 head0, 16-31 head1; each lane covers 4 channels.
__global__ void gat_h2(const int* __restrict__ rowptr, const int* __restrict__ csrc,
                       const float* __restrict__ as_, const float* __restrict__ ad_,
                       const float* __restrict__ hraw, const float* __restrict__ bias,
                       float* __restrict__ out, int n) {
    int d = (blockIdx.x * blockDim.x + threadIdx.x) >> 5;
    if (d >= n) return;
    int lane = threadIdx.x & 31;
    int half = lane >> 4, li = lane & 15;
    int begin = rowptr[d], end = rowptr[d + 1];
    float ad_h = __ldg(&ad_[d * 2 + half]);
    float as_d = __ldg(&as_[d * 2 + half]);
    float e_self = lrelu02(as_d + ad_h);
    // ---- max pass ----
    float m = e_self;
    for (int i = begin + li; i < end; i += 16) {
        int s = __ldg(&csrc[i]);
        m = fmaxf(m, lrelu02(__ldg(&as_[s * 2 + half]) + ad_h));
    }
#pragma unroll
    for (int o = 8; o; o >>= 1) m = fmaxf(m, __shfl_xor_sync(0xffffffffu, m, o));
    // ---- accumulate: serial over edges, 2-deep index prefetch ----
    float w0 = __expf(e_self - m);
    float4 hv = *(const float4*)&hraw[(size_t)d * 128 + lane * 4];
    float4 acc = make_float4(w0 * hv.x, w0 * hv.y, w0 * hv.z, w0 * hv.w);
    float den = (li == 0) ? w0 : 0.f;
    int s0 = (begin + 0 < end) ? __ldg(&csrc[begin + 0]) : 0;
    int s1 = (begin + 1 < end) ? __ldg(&csrc[begin + 1]) : 0;
    for (int i = begin; i < end; ++i) {
        int s = s0;
        s0 = s1;
        s1 = (i + 2 < end) ? __ldg(&csrc[i + 2]) : 0;
        float es = __ldg(&as_[s * 2 + half]);
        float4 v = *(const float4*)&hraw[(size_t)s * 128 + lane * 4];
        float w = __expf(lrelu02(es + ad_h) - m);
        acc.x = fmaf(w, v.x, acc.x); acc.y = fmaf(w, v.y, acc.y);
        acc.z = fmaf(w, v.z, acc.z); acc.w = fmaf(w, v.w, acc.w);
        if (li == 0) den += w;
    }
    float den_b = __shfl_sync(0xffffffffu, den, half << 4) + 1e-16f;
    float rinv = 1.f / den_b;
    float4 bq = *(const float4*)&bias[lane * 4];
    float4 o;
    o.x = acc.x * rinv + bq.x; o.y = acc.y * rinv + bq.y;
    o.z = acc.z * rinv + bq.z; o.w = acc.w * rinv + bq.w;
    o.x = o.x > 0.f ? o.x : expm1f(o.x);
    o.y = o.y > 0.f ? o.y : expm1f(o.y);
    o.z = o.z > 0.f ? o.z : expm1f(o.z);
    o.w = o.w > 0.f ? o.w : expm1f(o.w);
    *(float4*)&out[(size_t)d * 128 + lane * 4] = o;
}

// H=1: warp per dst, lane covers 2 channels (64 total).
__global__ void gat_h1(const int* __restrict__ rowptr, const int* __restrict__ csrc,
                       const float* __restrict__ as_, const float* __restrict__ ad_,
                       const float* __restrict__ hraw, const float* __restrict__ bias,
                       float* __restrict__ out, int n) {
    int d = (blockIdx.x * blockDim.x + threadIdx.x) >> 5;
    if (d >= n) return;
    int lane = threadIdx.x & 31;
    int begin = rowptr[d], end = rowptr[d + 1];
    float ad_d = __ldg(&ad_[d]);
    float e_self = lrelu02(__ldg(&as_[d]) + ad_d);
    float m = e_self;
    for (int i = begin + lane; i < end; i += 32) {
        int s = __ldg(&csrc[i]);
        m = fmaxf(m, lrelu02(__ldg(&as_[s]) + ad_d));
    }
#pragma unroll
    for (int o = 16; o; o >>= 1) m = fmaxf(m, __shfl_xor_sync(0xffffffffu, m, o));
    float w0 = __expf(e_self - m);
    float2 hv = *(const float2*)&hraw[(size_t)d * 64 + lane * 2];
    float2 acc = make_float2(w0 * hv.x, w0 * hv.y);
    float den = (lane == 0) ? w0 : 0.f;
    int s0 = (begin + 0 < end) ? __ldg(&csrc[begin + 0]) : 0;
    int s1 = (begin + 1 < end) ? __ldg(&csrc[begin + 1]) : 0;
    for (int i = begin; i < end; ++i) {
        int s = s0;
        s0 = s1;
        s1 = (i + 2 < end) ? __ldg(&csrc[i + 2]) : 0;
        float es = __ldg(&as_[s]);
        float2 v = *(const float2*)&hraw[(size_t)s * 64 + lane * 2];
        float w = __expf(lrelu02(es + ad_d) - m);
        acc.x = fmaf(w, v.x, acc.x);
        acc.y = fmaf(w, v.y, acc.y);
        if (lane == 0) den += w;
    }
    float den_b = __shfl_sync(0xffffffffu, den, 0) + 1e-16f;
    float rinv = 1.f / den_b;
    float2 bq = *(const float2*)&bias[lane * 2];
    float2 o;
    o.x = acc.x * rinv + bq.x; o.y = acc.y * rinv + bq.y;
    o.x = o.x > 0.f ? o.x : expm1f(o.x);
    o.y = o.y > 0.f ? o.y : expm1f(o.y);
    *(float2*)&out[(size_t)d * 64 + lane * 2] = o;
}

// ---------------- final linear + sigmoid -------------------------------------
__global__ void final_lin(const float* __restrict__ H2, const float* __restrict__ Lw,
                          const float* __restrict__ Lb, float* __restrict__ out, int n) {
    __shared__ float sw[64 * 16];
    __shared__ float sb[16];
    int tid = threadIdx.x;
    for (int idx = tid; idx < 64 * 16; idx += 256) sw[idx] = Lw[idx];
    if (tid < 16) sb[tid] = Lb[tid];
    __syncthreads();
    int gw = (blockIdx.x * 256 + tid) >> 5;
    int nw = (gridDim.x * 256) >> 5;
    int lane = tid & 31;
    int o = lane & 15, half = lane >> 4;
    for (int i = gw; i < n; i += nw) {
        const float* row = &H2[(size_t)i * 64 + half * 32];
        float acc = 0.f;
#pragma unroll
        for (int c = 0; c < 32; ++c) acc = fmaf(row[c], sw[(half * 32 + c) * 16 + o], acc);
        acc += __shfl_xor_sync(0xffffffffu, acc, 16);
        if (lane < 16) out[(size_t)i * 16 + o] = 1.f / (1.f + __expf(-(acc + sb[o])));
    }
}

// ---------------- launcher ---------------------------------------------------
static inline int cdiv(long long a, long long b) { return (int)((a + b - 1) / b); }

extern "C" void kernel_launch(void* const* d_in, const int* in_sizes, int n_in,
                              void* d_out, int out_size) {
    const float* x   = (const float*)d_in[0];
    const int*   ei  = (const int*)d_in[1];
    const float* W1  = (const float*)d_in[2];
    const float* As1 = (const float*)d_in[3];
    const float* Ad1 = (const float*)d_in[4];
    const float* b1  = (const float*)d_in[5];
    const float* W2  = (const float*)d_in[6];
    const float* As2 = (const float*)d_in[7];
    const float* Ad2 = (const float*)d_in[8];
    const float* b2  = (const float*)d_in[9];
    const float* lw  = (const float*)d_in[10];
    const float* lb  = (const float*)d_in[11];
    float*       out = (float*)d_out;

    int n = in_sizes[0] / 128;
    int E = in_sizes[1] / 2;
    const int* src = ei;
    const int* dst = ei + E;

    float *h1, *as1, *ad1, *x2, *h2, *as2, *ad2, *o2;
    int *cnt, *rowptr, *woff, *csrc;
    cudaGetSymbolAddress((void**)&h1, g_h1);
    cudaGetSymbolAddress((void**)&as1, g_as1); cudaGetSymbolAddress((void**)&ad1, g_ad1);
    cudaGetSymbolAddress((void**)&x2, g_x2);
    cudaGetSymbolAddress((void**)&h2, g_h2);
    cudaGetSymbolAddress((void**)&as2, g_as2); cudaGetSymbolAddress((void**)&ad2, g_ad2);
    cudaGetSymbolAddress((void**)&o2, g_o2);
    cudaGetSymbolAddress((void**)&cnt, g_cnt); cudaGetSymbolAddress((void**)&rowptr, g_rowptr);
    cudaGetSymbolAddress((void**)&woff, g_woff); cudaGetSymbolAddress((void**)&csrc, g_csrc);

    const int T = 256;

    // ---- CSR build (shared by both layers) ----
    zero_cnt<<<cdiv(n, T), T>>>(cnt, n);
    hist_dst<<<cdiv(E, T), T>>>(dst, cnt, E);
    scan_cnt<<<1, 1024>>>(cnt, rowptr, woff, n);
    csr_scatter<<<cdiv(E, T), T>>>(src, dst, woff, csrc, E);

    // ---- layer 1 (H=2, C=64, concat) ----
    gemm64<128><<<dim3(cdiv(n, 64), 2), T>>>(x, W1, h1, n);
    attn_h2<<<cdiv((long long)n * 32, T), T>>>(h1, As1, Ad1, as1, ad1, n);
    gat_h2<<<cdiv((long long)n * 32, T), T>>>(rowptr, csrc, as1, ad1, h1, b1, x2, n);

    // ---- layer 2 (H=1, C=64) ----
    gemm64<64><<<dim3(cdiv(n, 64), 1), T>>>(x2, W2, h2, n);
    attn_h1<<<cdiv((long long)n * 32, T), T>>>(h2, As2, Ad2, as2, ad2, n);
    gat_h1<<<cdiv((long long)n * 32, T), T>>>(rowptr, csrc, as2, ad2, h2, b2, o2, n);

    // ---- final linear + sigmoid ----
    final_lin<<<cdiv((long long)n * 32, T), T>>>(o2, lw, lb, out, n);
}

// round 8
// speedup vs baseline: 1.5721x; 1.0070x over previous
#include <cuda_runtime.h>
#include <cuda_bf16.h>
#include <math.h>

#define NMAX 50000
#define EMAX 800000

// ---------------- scratch ----------------------------------------------------
__device__ __align__(16) float g_h1[NMAX * 128];
__device__ __align__(16) float g_as1[NMAX * 2], g_ad1[NMAX * 2];
__device__ __align__(16) float g_x2[NMAX * 128];
__device__ __align__(16) float g_h2[NMAX * 64];
__device__ __align__(16) float g_as2[NMAX], g_ad2[NMAX];
__device__ __align__(16) float g_o2[NMAX * 64];
// CSR
__device__ int g_cnt[NMAX];
__device__ int g_rowptr[NMAX + 1];
__device__ int g_woff[NMAX];
__device__ int g_csrc[EMAX];

// ---------------- helpers ----------------------------------------------------
__device__ __forceinline__ float lrelu02(float x) { return x >= 0.f ? x : 0.2f * x; }

// ---------------- CSR build ---------------------------------------------------
__global__ void zero_cnt(int* cnt, int n) {
    int t = blockIdx.x * blockDim.x + threadIdx.x;
    if (t < n) cnt[t] = 0;
}
__global__ void hist_dst(const int* __restrict__ dst, int* __restrict__ cnt, int E) {
    int e = blockIdx.x * blockDim.x + threadIdx.x;
    if (e < E) atomicAdd(&cnt[dst[e]], 1);
}
// single-block chunked exclusive scan: each thread owns a contiguous chunk.
__global__ void scan_cnt(const int* __restrict__ cnt, int* __restrict__ rowptr,
                         int* __restrict__ woff, int n) {
    __shared__ int warpsum[32];
    int tid = threadIdx.x, lane = tid & 31, wid = tid >> 5;
    const int CHUNK = (n + 1023) >> 10;
    int b = tid * CHUNK;
    int e = b + CHUNK; if (e > n) e = n;
    int s = 0;
    for (int i = b; i < e; ++i) s += cnt[i];
    // block-wide inclusive scan of per-thread sums
    int x = s;
#pragma unroll
    for (int o = 1; o < 32; o <<= 1) {
        int y = __shfl_up_sync(0xffffffffu, x, o);
        if (lane >= o) x += y;
    }
    if (lane == 31) warpsum[wid] = x;
    __syncthreads();
    if (wid == 0) {
        int w = warpsum[lane];
#pragma unroll
        for (int o = 1; o < 32; o <<= 1) {
            int y = __shfl_up_sync(0xffffffffu, w, o);
            if (lane >= o) w += y;
        }
        warpsum[lane] = w;
    }
    __syncthreads();
    int excl = x - s + (wid > 0 ? warpsum[wid - 1] : 0);
    int run = excl;
    for (int i = b; i < e; ++i) {
        rowptr[i] = run; woff[i] = run;
        run += cnt[i];
    }
    if (tid == 1023) rowptr[n] = run;
}
__global__ void csr_scatter(const int* __restrict__ src, const int* __restrict__ dst,
                            int* __restrict__ woff, int* __restrict__ csrc, int E) {
    int e = blockIdx.x * blockDim.x + threadIdx.x;
    if (e < E) {
        int d = dst[e];
        int p = atomicAdd(&woff[d], 1);
        csrc[p] = src[e];
    }
}

// ---------------- GEMM: 64x64 tile, 4x4 register blocking --------------------
template <int OUT>
__global__ void gemm64(const float* __restrict__ X, const float* __restrict__ Wg,
                       float* __restrict__ Hout, int n) {
    __shared__ float sA[64][68];   // [k][row], padded
    __shared__ float sB[64][64];   // [k][col]
    const int tid = threadIdx.x;
    const int tx = tid & 15, ty = tid >> 4;
    const int rowBase = blockIdx.x * 64, colBase = blockIdx.y * 64;
    float acc[4][4] = {};
    for (int kt = 0; kt < 2; ++kt) {
        for (int idx = tid; idx < 64 * 16; idx += 256) {
            int r = idx >> 4, kq = idx & 15;
            int row = rowBase + r;
            float4 v = make_float4(0.f, 0.f, 0.f, 0.f);
            if (row < n) v = *(const float4*)&X[(size_t)row * 128 + kt * 64 + kq * 4];
            sA[kq * 4 + 0][r] = v.x; sA[kq * 4 + 1][r] = v.y;
            sA[kq * 4 + 2][r] = v.z; sA[kq * 4 + 3][r] = v.w;
        }
        for (int idx = tid; idx < 64 * 16; idx += 256) {
            int k = idx >> 4, cq = idx & 15;
            *(float4*)&sB[k][cq * 4] =
                *(const float4*)&Wg[(size_t)(kt * 64 + k) * OUT + colBase + cq * 4];
        }
        __syncthreads();
#pragma unroll
        for (int k = 0; k < 64; ++k) {
            float a[4], b[4];
            *(float4*)a = *(const float4*)&sA[k][ty * 4];
            *(float4*)b = *(const float4*)&sB[k][tx * 4];
#pragma unroll
            for (int i = 0; i < 4; ++i)
#pragma unroll
                for (int j = 0; j < 4; ++j)
                    acc[i][j] = fmaf(a[i], b[j], acc[i][j]);
        }
        __syncthreads();
    }
#pragma unroll
    for (int i = 0; i < 4; ++i) {
        int row = rowBase + ty * 4 + i;
        if (row < n)
            *(float4*)&Hout[(size_t)row * OUT + colBase + tx * 4] =
                make_float4(acc[i][0], acc[i][1], acc[i][2], acc[i][3]);
    }
}

// ---------------- attention scores -------------------------------------------
__global__ void attn_h2(const float* __restrict__ Hm, const float* __restrict__ As,
                        const float* __restrict__ Ad, float* __restrict__ as_,
                        float* __restrict__ ad_, int n) {
    int gw = (blockIdx.x * blockDim.x + threadIdx.x) >> 5;
    int nw = (gridDim.x * blockDim.x) >> 5;
    int lane = threadIdx.x & 31;
    float4 s4 = *(const float4*)&As[lane * 4];
    float4 d4 = *(const float4*)&Ad[lane * 4];
    for (int i = gw; i < n; i += nw) {
        float4 v = *(const float4*)&Hm[(size_t)i * 128 + lane * 4];
        float ps = v.x * s4.x + v.y * s4.y + v.z * s4.z + v.w * s4.w;
        float pd = v.x * d4.x + v.y * d4.y + v.z * d4.z + v.w * d4.w;
#pragma unroll
        for (int o = 8; o; o >>= 1) {
            ps += __shfl_xor_sync(0xffffffffu, ps, o);
            pd += __shfl_xor_sync(0xffffffffu, pd, o);
        }
        if ((lane & 15) == 0) {
            as_[i * 2 + (lane >> 4)] = ps;
            ad_[i * 2 + (lane >> 4)] = pd;
        }
    }
}
__global__ void attn_h1(const float* __restrict__ Hm, const float* __restrict__ As,
                        const float* __restrict__ Ad, float* __restrict__ as_,
                        float* __restrict__ ad_, int n) {
    int gw = (blockIdx.x * blockDim.x + threadIdx.x) >> 5;
    int nw = (gridDim.x * blockDim.x) >> 5;
    int lane = threadIdx.x & 31;
    float2 s2 = *(const float2*)&As[lane * 2];
    float2 d2 = *(const float2*)&Ad[lane * 2];
    for (int i = gw; i < n; i += nw) {
        float2 v = *(const float2*)&Hm[(size_t)i * 64 + lane * 2];
        float ps = v.x * s2.x + v.y * s2.y;
        float pd = v.x * d2.x + v.y * d2.y;
#pragma unroll
        for (int o = 16; o; o >>= 1) {
            ps += __shfl_xor_sync(0xffffffffu, ps, o);
            pd += __shfl_xor_sync(0xffffffffu, pd, o);
        }
        if (lane == 0) { as_[i] = ps; ad_[i] = pd; }
    }
}

// ---------------- fused GAT softmax-aggregate, NO max pass --------------------
// softmax is shift-invariant; e = as+ad is O(1..10), exp() cannot overflow fp32.
// H=2: lanes 0-15 head0, 16-31 head1; each lane covers 4 channels.
__global__ void gat_h2(const int* __restrict__ rowptr, const int* __restrict__ csrc,
                       const float* __restrict__ as_, const float* __restrict__ ad_,
                       const float* __restrict__ hraw, const float* __restrict__ bias,
                       float* __restrict__ out, int n) {
    int d = (blockIdx.x * blockDim.x + threadIdx.x) >> 5;
    if (d >= n) return;
    int lane = threadIdx.x & 31;
    int half = lane >> 4, li = lane & 15;
    int begin = rowptr[d], end = rowptr[d + 1];
    float ad_h = __ldg(&ad_[d * 2 + half]);
    float w0 = __expf(lrelu02(__ldg(&as_[d * 2 + half]) + ad_h));   // self-loop
    float4 hv = *(const float4*)&hraw[(size_t)d * 128 + lane * 4];
    float4 acc = make_float4(w0 * hv.x, w0 * hv.y, w0 * hv.z, w0 * hv.w);
    float den = (li == 0) ? w0 : 0.f;
    int i = begin;
    // 2-wide unroll: two independent gather chains per iteration
    for (; i + 1 < end; i += 2) {
        int sA = __ldg(&csrc[i]);
        int sB = __ldg(&csrc[i + 1]);
        float eA = __ldg(&as_[sA * 2 + half]);
        float eB = __ldg(&as_[sB * 2 + half]);
        float4 vA = *(const float4*)&hraw[(size_t)sA * 128 + lane * 4];
        float4 vB = *(const float4*)&hraw[(size_t)sB * 128 + lane * 4];
        float wA = __expf(lrelu02(eA + ad_h));
        float wB = __expf(lrelu02(eB + ad_h));
        acc.x = fmaf(wA, vA.x, acc.x); acc.y = fmaf(wA, vA.y, acc.y);
        acc.z = fmaf(wA, vA.z, acc.z); acc.w = fmaf(wA, vA.w, acc.w);
        acc.x = fmaf(wB, vB.x, acc.x); acc.y = fmaf(wB, vB.y, acc.y);
        acc.z = fmaf(wB, vB.z, acc.z); acc.w = fmaf(wB, vB.w, acc.w);
        if (li == 0) den += wA + wB;
    }
    if (i < end) {
        int s = __ldg(&csrc[i]);
        float es = __ldg(&as_[s * 2 + half]);
        float4 v = *(const float4*)&hraw[(size_t)s * 128 + lane * 4];
        float w = __expf(lrelu02(es + ad_h));
        acc.x = fmaf(w, v.x, acc.x); acc.y = fmaf(w, v.y, acc.y);
        acc.z = fmaf(w, v.z, acc.z); acc.w = fmaf(w, v.w, acc.w);
        if (li == 0) den += w;
    }
    float den_b = __shfl_sync(0xffffffffu, den, half << 4) + 1e-16f;
    float rinv = 1.f / den_b;
    float4 bq = *(const float4*)&bias[lane * 4];
    float4 o;
    o.x = acc.x * rinv + bq.x; o.y = acc.y * rinv + bq.y;
    o.z = acc.z * rinv + bq.z; o.w = acc.w * rinv + bq.w;
    o.x = o.x > 0.f ? o.x : expm1f(o.x);
    o.y = o.y > 0.f ? o.y : expm1f(o.y);
    o.z = o.z > 0.f ? o.z : expm1f(o.z);
    o.w = o.w > 0.f ? o.w : expm1f(o.w);
    *(float4*)&out[(size_t)d * 128 + lane * 4] = o;
}

// H=1: warp per dst, lane covers 2 channels (64 total).
__global__ void gat_h1(const int* __restrict__ rowptr, const int* __restrict__ csrc,
                       const float* __restrict__ as_, const float* __restrict__ ad_,
                       const float* __restrict__ hraw, const float* __restrict__ bias,
                       float* __restrict__ out, int n) {
    int d = (blockIdx.x * blockDim.x + threadIdx.x) >> 5;
    if (d >= n) return;
    int lane = threadIdx.x & 31;
    int begin = rowptr[d], end = rowptr[d + 1];
    float ad_d = __ldg(&ad_[d]);
    float w0 = __expf(lrelu02(__ldg(&as_[d]) + ad_d));
    float2 hv = *(const float2*)&hraw[(size_t)d * 64 + lane * 2];
    float2 acc = make_float2(w0 * hv.x, w0 * hv.y);
    float den = (lane == 0) ? w0 : 0.f;
    int i = begin;
    for (; i + 1 < end; i += 2) {
        int sA = __ldg(&csrc[i]);
        int sB = __ldg(&csrc[i + 1]);
        float eA = __ldg(&as_[sA]);
        float eB = __ldg(&as_[sB]);
        float2 vA = *(const float2*)&hraw[(size_t)sA * 64 + lane * 2];
        float2 vB = *(const float2*)&hraw[(size_t)sB * 64 + lane * 2];
        float wA = __expf(lrelu02(eA + ad_d));
        float wB = __expf(lrelu02(eB + ad_d));
        acc.x = fmaf(wA, vA.x, acc.x); acc.y = fmaf(wA, vA.y, acc.y);
        acc.x = fmaf(wB, vB.x, acc.x); acc.y = fmaf(wB, vB.y, acc.y);
        if (lane == 0) den += wA + wB;
    }
    if (i < end) {
        int s = __ldg(&csrc[i]);
        float es = __ldg(&as_[s]);
        float2 v = *(const float2*)&hraw[(size_t)s * 64 + lane * 2];
        float w = __expf(lrelu02(es + ad_d));
        acc.x = fmaf(w, v.x, acc.x);
        acc.y = fmaf(w, v.y, acc.y);
        if (lane == 0) den += w;
    }
    float den_b = __shfl_sync(0xffffffffu, den, 0) + 1e-16f;
    float rinv = 1.f / den_b;
    float2 bq = *(const float2*)&bias[lane * 2];
    float2 o;
    o.x = acc.x * rinv + bq.x; o.y = acc.y * rinv + bq.y;
    o.x = o.x > 0.f ? o.x : expm1f(o.x);
    o.y = o.y > 0.f ? o.y : expm1f(o.y);
    *(float2*)&out[(size_t)d * 64 + lane * 2] = o;
}

// ---------------- final linear + sigmoid -------------------------------------
__global__ void final_lin(const float* __restrict__ H2, const float* __restrict__ Lw,
                          const float* __restrict__ Lb, float* __restrict__ out, int n) {
    __shared__ float sw[64 * 16];
    __shared__ float sb[16];
    int tid = threadIdx.x;
    for (int idx = tid; idx < 64 * 16; idx += 256) sw[idx] = Lw[idx];
    if (tid < 16) sb[tid] = Lb[tid];
    __syncthreads();
    int gw = (blockIdx.x * 256 + tid) >> 5;
    int nw = (gridDim.x * 256) >> 5;
    int lane = tid & 31;
    int o = lane & 15, half = lane >> 4;
    for (int i = gw; i < n; i += nw) {
        const float* row = &H2[(size_t)i * 64 + half * 32];
        float acc = 0.f;
#pragma unroll
        for (int c = 0; c < 32; ++c) acc = fmaf(row[c], sw[(half * 32 + c) * 16 + o], acc);
        acc += __shfl_xor_sync(0xffffffffu, acc, 16);
        if (lane < 16) out[(size_t)i * 16 + o] = 1.f / (1.f + __expf(-(acc + sb[o])));
    }
}

// ---------------- launcher ---------------------------------------------------
static inline int cdiv(long long a, long long b) { return (int)((a + b - 1) / b); }

extern "C" void kernel_launch(void* const* d_in, const int* in_sizes, int n_in,
                              void* d_out, int out_size) {
    const float* x   = (const float*)d_in[0];
    const int*   ei  = (const int*)d_in[1];
    const float* W1  = (const float*)d_in[2];
    const float* As1 = (const float*)d_in[3];
    const float* Ad1 = (const float*)d_in[4];
    const float* b1  = (const float*)d_in[5];
    const float* W2  = (const float*)d_in[6];
    const float* As2 = (const float*)d_in[7];
    const float* Ad2 = (const float*)d_in[8];
    const float* b2  = (const float*)d_in[9];
    const float* lw  = (const float*)d_in[10];
    const float* lb  = (const float*)d_in[11];
    float*       out = (float*)d_out;

    int n = in_sizes[0] / 128;
    int E = in_sizes[1] / 2;
    const int* src = ei;
    const int* dst = ei + E;

    float *h1, *as1, *ad1, *x2, *h2, *as2, *ad2, *o2;
    int *cnt, *rowptr, *woff, *csrc;
    cudaGetSymbolAddress((void**)&h1, g_h1);
    cudaGetSymbolAddress((void**)&as1, g_as1); cudaGetSymbolAddress((void**)&ad1, g_ad1);
    cudaGetSymbolAddress((void**)&x2, g_x2);
    cudaGetSymbolAddress((void**)&h2, g_h2);
    cudaGetSymbolAddress((void**)&as2, g_as2); cudaGetSymbolAddress((void**)&ad2, g_ad2);
    cudaGetSymbolAddress((void**)&o2, g_o2);
    cudaGetSymbolAddress((void**)&cnt, g_cnt); cudaGetSymbolAddress((void**)&rowptr, g_rowptr);
    cudaGetSymbolAddress((void**)&woff, g_woff); cudaGetSymbolAddress((void**)&csrc, g_csrc);

    const int T = 256;

    // ---- CSR build (shared by both layers) ----
    zero_cnt<<<cdiv(n, T), T>>>(cnt, n);
    hist_dst<<<cdiv(E, T), T>>>(dst, cnt, E);
    scan_cnt<<<1, 1024>>>(cnt, rowptr, woff, n);
    csr_scatter<<<cdiv(E, T), T>>>(src, dst, woff, csrc, E);

    // ---- layer 1 (H=2, C=64, concat) ----
    gemm64<128><<<dim3(cdiv(n, 64), 2), T>>>(x, W1, h1, n);
    attn_h2<<<cdiv((long long)n * 32, T), T>>>(h1, As1, Ad1, as1, ad1, n);
    gat_h2<<<cdiv((long long)n * 32, T), T>>>(rowptr, csrc, as1, ad1, h1, b1, x2, n);

    // ---- layer 2 (H=1, C=64) ----
    gemm64<64><<<dim3(cdiv(n, 64), 1), T>>>(x2, W2, h2, n);
    attn_h1<<<cdiv((long long)n * 32, T), T>>>(h2, As2, Ad2, as2, ad2, n);
    gat_h1<<<cdiv((long long)n * 32, T), T>>>(rowptr, csrc, as2, ad2, h2, b2, o2, n);

    // ---- final linear + sigmoid ----
    final_lin<<<cdiv((long long)n * 32, T), T>>>(o2, lw, lb, out, n);
}

// round 12
// speedup vs baseline: 1.6082x; 1.0230x over previous
#include <cuda_runtime.h>
#include <cuda_fp16.h>
#include <math.h>

#define NMAX 50000
#define EMAX 800000

// ---------------- scratch ----------------------------------------------------
__device__ __align__(16) __half g_h1h[NMAX * 128];   // layer1 features, fp16
__device__ __align__(16) float  g_as1[NMAX * 2], g_ad1[NMAX * 2];
__device__ __align__(16) float  g_x2[NMAX * 128];    // elu(layer1 out), fp32
__device__ __align__(16) __half g_h2h[NMAX * 64];    // layer2 features, fp16
__device__ __align__(16) float  g_as2[NMAX], g_ad2[NMAX];
__device__ __align__(16) float  g_o2[NMAX * 64];
// CSR
__device__ int g_cnt[NMAX];
__device__ int g_rowptr[NMAX + 1];
__device__ int g_woff[NMAX];
__device__ int g_csrc[EMAX];

// ---------------- helpers ----------------------------------------------------
__device__ __forceinline__ float lrelu02(float x) { return x >= 0.f ? x : 0.2f * x; }

// ---------------- CSR build ---------------------------------------------------
__global__ void zero_cnt(int* cnt, int n) {
    int t = blockIdx.x * blockDim.x + threadIdx.x;
    if (t < n) cnt[t] = 0;
}
__global__ void hist_dst(const int* __restrict__ dst, int* __restrict__ cnt, int E) {
    int e = blockIdx.x * blockDim.x + threadIdx.x;
    if (e < E) atomicAdd(&cnt[dst[e]], 1);
}
// single-block chunked exclusive scan
__global__ void scan_cnt(const int* __restrict__ cnt, int* __restrict__ rowptr,
                         int* __restrict__ woff, int n) {
    __shared__ int warpsum[32];
    int tid = threadIdx.x, lane = tid & 31, wid = tid >> 5;
    const int CHUNK = (n + 1023) >> 10;
    int b = tid * CHUNK;
    int e = b + CHUNK; if (e > n) e = n;
    int s = 0;
    for (int i = b; i < e; ++i) s += cnt[i];
    int x = s;
#pragma unroll
    for (int o = 1; o < 32; o <<= 1) {
        int y = __shfl_up_sync(0xffffffffu, x, o);
        if (lane >= o) x += y;
    }
    if (lane == 31) warpsum[wid] = x;
    __syncthreads();
    if (wid == 0) {
        int w = warpsum[lane];
#pragma unroll
        for (int o = 1; o < 32; o <<= 1) {
            int y = __shfl_up_sync(0xffffffffu, w, o);
            if (lane >= o) w += y;
        }
        warpsum[lane] = w;
    }
    __syncthreads();
    int run = x - s + (wid > 0 ? warpsum[wid - 1] : 0);
    for (int i = b; i < e; ++i) {
        rowptr[i] = run; woff[i] = run;
        run += cnt[i];
    }
    if (tid == 1023) rowptr[n] = run;
}
__global__ void csr_scatter(const int* __restrict__ src, const int* __restrict__ dst,
                            int* __restrict__ woff, int* __restrict__ csrc, int E) {
    int e = blockIdx.x * blockDim.x + threadIdx.x;
    if (e < E) {
        int d = dst[e];
        int p = atomicAdd(&woff[d], 1);
        csrc[p] = src[e];
    }
}

// ------- GEMM 64x64 tile + fused attention epilogue + fp16 feature store ------
// H[n,OUT] = X[n,128] @ W[128,OUT]; one 64-col head chunk per blockIdx.y.
// Epilogue: as/ad = fp32 dot of the row with att vectors (exact), h -> fp16.
template <int OUT>
__global__ void gemm64_fused(const float* __restrict__ X, const float* __restrict__ Wg,
                             const float* __restrict__ As, const float* __restrict__ Ad,
                             __half* __restrict__ Hh, float* __restrict__ as_,
                             float* __restrict__ ad_, int n) {
    const int NH = OUT / 64;               // heads
    __shared__ float sA[64][68];
    __shared__ float sB[64][64];
    const int tid = threadIdx.x;
    const int tx = tid & 15, ty = tid >> 4;
    const int rowBase = blockIdx.x * 64, colBase = blockIdx.y * 64;
    const int head = blockIdx.y;
    float acc[4][4] = {};
    for (int kt = 0; kt < 2; ++kt) {
        for (int idx = tid; idx < 64 * 16; idx += 256) {
            int r = idx >> 4, kq = idx & 15;
            int row = rowBase + r;
            float4 v = make_float4(0.f, 0.f, 0.f, 0.f);
            if (row < n) v = *(const float4*)&X[(size_t)row * 128 + kt * 64 + kq * 4];
            sA[kq * 4 + 0][r] = v.x; sA[kq * 4 + 1][r] = v.y;
            sA[kq * 4 + 2][r] = v.z; sA[kq * 4 + 3][r] = v.w;
        }
        for (int idx = tid; idx < 64 * 16; idx += 256) {
            int k = idx >> 4, cq = idx & 15;
            *(float4*)&sB[k][cq * 4] =
                *(const float4*)&Wg[(size_t)(kt * 64 + k) * OUT + colBase + cq * 4];
        }
        __syncthreads();
#pragma unroll
        for (int k = 0; k < 64; ++k) {
            float a[4], b[4];
            *(float4*)a = *(const float4*)&sA[k][ty * 4];
            *(float4*)b = *(const float4*)&sB[k][tx * 4];
#pragma unroll
            for (int i = 0; i < 4; ++i)
#pragma unroll
                for (int j = 0; j < 4; ++j)
                    acc[i][j] = fmaf(a[i], b[j], acc[i][j]);
        }
        __syncthreads();
    }
    // epilogue: attention dots (fp32 exact) + fp16 store
    float4 avs = *(const float4*)&As[head * 64 + tx * 4];
    float4 avd = *(const float4*)&Ad[head * 64 + tx * 4];
#pragma unroll
    for (int i = 0; i < 4; ++i) {
        int row = rowBase + ty * 4 + i;
        float ps = acc[i][0] * avs.x + acc[i][1] * avs.y + acc[i][2] * avs.z + acc[i][3] * avs.w;
        float pd = acc[i][0] * avd.x + acc[i][1] * avd.y + acc[i][2] * avd.z + acc[i][3] * avd.w;
#pragma unroll
        for (int o = 1; o < 16; o <<= 1) {
            ps += __shfl_xor_sync(0xffffffffu, ps, o);
            pd += __shfl_xor_sync(0xffffffffu, pd, o);
        }
        if (row < n) {
            if (tx == 0) {
                as_[row * NH + head] = ps;
                ad_[row * NH + head] = pd;
            }
            __half2 p0 = __floats2half2_rn(acc[i][0], acc[i][1]);
            __half2 p1 = __floats2half2_rn(acc[i][2], acc[i][3]);
            uint2 u;
            u.x = *(unsigned*)&p0; u.y = *(unsigned*)&p1;
            *(uint2*)&Hh[(size_t)row * OUT + colBase + tx * 4] = u;
        }
    }
}

// ---------------- fused GAT softmax-aggregate (fp16 gather) -------------------
// H=2: lanes 0-15 head0, 16-31 head1; each lane covers 4 channels (8B fp16).
__global__ void gat_h2(const int* __restrict__ rowptr, const int* __restrict__ csrc,
                       const float* __restrict__ as_, const float* __restrict__ ad_,
                       const __half* __restrict__ hh, const float* __restrict__ bias,
                       float* __restrict__ out, int n) {
    int d = (blockIdx.x * blockDim.x + threadIdx.x) >> 5;
    if (d >= n) return;
    int lane = threadIdx.x & 31;
    int half = lane >> 4, li = lane & 15;
    int begin = rowptr[d], end = rowptr[d + 1];
    float ad_h = __ldg(&ad_[d * 2 + half]);
    float w0 = __expf(lrelu02(__ldg(&as_[d * 2 + half]) + ad_h));   // self-loop
    uint2 hu = *(const uint2*)&hh[(size_t)d * 128 + lane * 4];
    float2 h0 = __half22float2(*(__half2*)&hu.x);
    float2 h1 = __half22float2(*(__half2*)&hu.y);
    float4 acc = make_float4(w0 * h0.x, w0 * h0.y, w0 * h1.x, w0 * h1.y);
    float den = (li == 0) ? w0 : 0.f;
    int i = begin;
    for (; i + 1 < end; i += 2) {
        int sA = __ldg(&csrc[i]);
        int sB = __ldg(&csrc[i + 1]);
        float eA = __ldg(&as_[sA * 2 + half]);
        float eB = __ldg(&as_[sB * 2 + half]);
        uint2 uA = *(const uint2*)&hh[(size_t)sA * 128 + lane * 4];
        uint2 uB = *(const uint2*)&hh[(size_t)sB * 128 + lane * 4];
        float wA = __expf(lrelu02(eA + ad_h));
        float wB = __expf(lrelu02(eB + ad_h));
        float2 a0 = __half22float2(*(__half2*)&uA.x);
        float2 a1 = __half22float2(*(__half2*)&uA.y);
        float2 b0 = __half22float2(*(__half2*)&uB.x);
        float2 b1 = __half22float2(*(__half2*)&uB.y);
        acc.x = fmaf(wA, a0.x, acc.x); acc.y = fmaf(wA, a0.y, acc.y);
        acc.z = fmaf(wA, a1.x, acc.z); acc.w = fmaf(wA, a1.y, acc.w);
        acc.x = fmaf(wB, b0.x, acc.x); acc.y = fmaf(wB, b0.y, acc.y);
        acc.z = fmaf(wB, b1.x, acc.z); acc.w = fmaf(wB, b1.y, acc.w);
        if (li == 0) den += wA + wB;
    }
    if (i < end) {
        int s = __ldg(&csrc[i]);
        float es = __ldg(&as_[s * 2 + half]);
        uint2 u = *(const uint2*)&hh[(size_t)s * 128 + lane * 4];
        float w = __expf(lrelu02(es + ad_h));
        float2 a0 = __half22float2(*(__half2*)&u.x);
        float2 a1 = __half22float2(*(__half2*)&u.y);
        acc.x = fmaf(w, a0.x, acc.x); acc.y = fmaf(w, a0.y, acc.y);
        acc.z = fmaf(w, a1.x, acc.z); acc.w = fmaf(w, a1.y, acc.w);
        if (li == 0) den += w;
    }
    float den_b = __shfl_sync(0xffffffffu, den, half << 4) + 1e-16f;
    float rinv = 1.f / den_b;
    float4 bq = *(const float4*)&bias[lane * 4];
    float4 o;
    o.x = acc.x * rinv + bq.x; o.y = acc.y * rinv + bq.y;
    o.z = acc.z * rinv + bq.z; o.w = acc.w * rinv + bq.w;
    o.x = o.x > 0.f ? o.x : expm1f(o.x);
    o.y = o.y > 0.f ? o.y : expm1f(o.y);
    o.z = o.z > 0.f ? o.z : expm1f(o.z);
    o.w = o.w > 0.f ? o.w : expm1f(o.w);
    *(float4*)&out[(size_t)d * 128 + lane * 4] = o;
}

// H=1: warp per dst, lane covers 2 channels (4B fp16).
__global__ void gat_h1(const int* __restrict__ rowptr, const int* __restrict__ csrc,
                       const float* __restrict__ as_, const float* __restrict__ ad_,
                       const __half* __restrict__ hh, const float* __restrict__ bias,
                       float* __restrict__ out, int n) {
    int d = (blockIdx.x * blockDim.x + threadIdx.x) >> 5;
    if (d >= n) return;
    int lane = threadIdx.x & 31;
    int begin = rowptr[d], end = rowptr[d + 1];
    float ad_d = __ldg(&ad_[d]);
    float w0 = __expf(lrelu02(__ldg(&as_[d]) + ad_d));
    float2 hv = __half22float2(*(const __half2*)&hh[(size_t)d * 64 + lane * 2]);
    float2 acc = make_float2(w0 * hv.x, w0 * hv.y);
    float den = (lane == 0) ? w0 : 0.f;
    int i = begin;
    for (; i + 1 < end; i += 2) {
        int sA = __ldg(&csrc[i]);
        int sB = __ldg(&csrc[i + 1]);
        float eA = __ldg(&as_[sA]);
        float eB = __ldg(&as_[sB]);
        float2 vA = __half22float2(*(const __half2*)&hh[(size_t)sA * 64 + lane * 2]);
        float2 vB = __half22float2(*(const __half2*)&hh[(size_t)sB * 64 + lane * 2]);
        float wA = __expf(lrelu02(eA + ad_d));
        float wB = __expf(lrelu02(eB + ad_d));
        acc.x = fmaf(wA, vA.x, acc.x); acc.y = fmaf(wA, vA.y, acc.y);
        acc.x = fmaf(wB, vB.x, acc.x); acc.y = fmaf(wB, vB.y, acc.y);
        if (lane == 0) den += wA + wB;
    }
    if (i < end) {
        int s = __ldg(&csrc[i]);
        float es = __ldg(&as_[s]);
        float2 v = __half22float2(*(const __half2*)&hh[(size_t)s * 64 + lane * 2]);
        float w = __expf(lrelu02(es + ad_d));
        acc.x = fmaf(w, v.x, acc.x);
        acc.y = fmaf(w, v.y, acc.y);
        if (lane == 0) den += w;
    }
    float den_b = __shfl_sync(0xffffffffu, den, 0) + 1e-16f;
    float rinv = 1.f / den_b;
    float2 bq = *(const float2*)&bias[lane * 2];
    float2 o;
    o.x = acc.x * rinv + bq.x; o.y = acc.y * rinv + bq.y;
    o.x = o.x > 0.f ? o.x : expm1f(o.x);
    o.y = o.y > 0.f ? o.y : expm1f(o.y);
    *(float2*)&out[(size_t)d * 64 + lane * 2] = o;
}

// ---------------- final linear + sigmoid -------------------------------------
__global__ void final_lin(const float* __restrict__ H2, const float* __restrict__ Lw,
                          const float* __restrict__ Lb, float* __restrict__ out, int n) {
    __shared__ float sw[64 * 16];
    __shared__ float sb[16];
    int tid = threadIdx.x;
    for (int idx = tid; idx < 64 * 16; idx += 256) sw[idx] = Lw[idx];
    if (tid < 16) sb[tid] = Lb[tid];
    __syncthreads();
    int gw = (blockIdx.x * 256 + tid) >> 5;
    int nw = (gridDim.x * 256) >> 5;
    int lane = tid & 31;
    int o = lane & 15, half = lane >> 4;
    for (int i = gw; i < n; i += nw) {
        const float* row = &H2[(size_t)i * 64 + half * 32];
        float acc = 0.f;
#pragma unroll
        for (int c = 0; c < 32; ++c) acc = fmaf(row[c], sw[(half * 32 + c) * 16 + o], acc);
        acc += __shfl_xor_sync(0xffffffffu, acc, 16);
        if (lane < 16) out[(size_t)i * 16 + o] = 1.f / (1.f + __expf(-(acc + sb[o])));
    }
}

// ---------------- launcher ---------------------------------------------------
static inline int cdiv(long long a, long long b) { return (int)((a + b - 1) / b); }

extern "C" void kernel_launch(void* const* d_in, const int* in_sizes, int n_in,
                              void* d_out, int out_size) {
    const float* x   = (const float*)d_in[0];
    const int*   ei  = (const int*)d_in[1];
    const float* W1  = (const float*)d_in[2];
    const float* As1 = (const float*)d_in[3];
    const float* Ad1 = (const float*)d_in[4];
    const float* b1  = (const float*)d_in[5];
    const float* W2  = (const float*)d_in[6];
    const float* As2 = (const float*)d_in[7];
    const float* Ad2 = (const float*)d_in[8];
    const float* b2  = (const float*)d_in[9];
    const float* lw  = (const float*)d_in[10];
    const float* lb  = (const float*)d_in[11];
    float*       out = (float*)d_out;

    int n = in_sizes[0] / 128;
    int E = in_sizes[1] / 2;
    const int* src = ei;
    const int* dst = ei + E;

    __half *h1h, *h2h;
    float *as1, *ad1, *x2, *as2, *ad2, *o2;
    int *cnt, *rowptr, *woff, *csrc;
    cudaGetSymbolAddress((void**)&h1h, g_h1h);
    cudaGetSymbolAddress((void**)&as1, g_as1); cudaGetSymbolAddress((void**)&ad1, g_ad1);
    cudaGetSymbolAddress((void**)&x2, g_x2);
    cudaGetSymbolAddress((void**)&h2h, g_h2h);
    cudaGetSymbolAddress((void**)&as2, g_as2); cudaGetSymbolAddress((void**)&ad2, g_ad2);
    cudaGetSymbolAddress((void**)&o2, g_o2);
    cudaGetSymbolAddress((void**)&cnt, g_cnt); cudaGetSymbolAddress((void**)&rowptr, g_rowptr);
    cudaGetSymbolAddress((void**)&woff, g_woff); cudaGetSymbolAddress((void**)&csrc, g_csrc);

    const int T = 256;

    // ---- CSR build (shared by both layers) ----
    zero_cnt<<<cdiv(n, T), T>>>(cnt, n);
    hist_dst<<<cdiv(E, T), T>>>(dst, cnt, E);
    scan_cnt<<<1, 1024>>>(cnt, rowptr, woff, n);
    csr_scatter<<<cdiv(E, T), T>>>(src, dst, woff, csrc, E);

    // ---- layer 1 (H=2, C=64, concat) ----
    gemm64_fused<128><<<dim3(cdiv(n, 64), 2), T>>>(x, W1, As1, Ad1, h1h, as1, ad1, n);
    gat_h2<<<cdiv((long long)n * 32, T), T>>>(rowptr, csrc, as1, ad1, h1h, b1, x2, n);

    // ---- layer 2 (H=1, C=64) ----
    gemm64_fused<64><<<dim3(cdiv(n, 64), 1), T>>>(x2, W2, As2, Ad2, h2h, as2, ad2, n);
    gat_h1<<<cdiv((long long)n * 32, T), T>>>(rowptr, csrc, as2, ad2, h2h, b2, o2, n);

    // ---- final linear + sigmoid ----
    final_lin<<<cdiv((long long)n * 32, T), T>>>(o2, lw, lb, out, n);
}

// round 15
// speedup vs baseline: 1.8954x; 1.1786x over previous
#include <cuda_runtime.h>
#include <cuda_fp16.h>
#include <math.h>

#define NMAX 50000
#define EMAX 800000

// ---------------- scratch ----------------------------------------------------
__device__ __align__(16) __half g_h1h[NMAX * 128];
__device__ __align__(16) float  g_as1[NMAX * 2], g_ad1[NMAX * 2];
__device__ __align__(16) float  g_x2[NMAX * 128];
__device__ __align__(16) __half g_h2h[NMAX * 64];
__device__ __align__(16) float  g_as2[NMAX], g_ad2[NMAX];
__device__ __align__(16) float  g_o2[NMAX * 64];
__device__ int g_cnt[NMAX];
__device__ int g_rowptr[NMAX + 1];
__device__ int g_woff[NMAX];
__device__ int g_csrc[EMAX];

__device__ __forceinline__ float lrelu02(float x) { return x >= 0.f ? x : 0.2f * x; }

// ---------------- CSR build ---------------------------------------------------
__global__ void hist_dst(const int* __restrict__ dst, int* __restrict__ cnt, int E) {
    int e = blockIdx.x * blockDim.x + threadIdx.x;
    if (e < E) atomicAdd(&cnt[dst[e]], 1);
}
__global__ void scan_cnt(const int* __restrict__ cnt, int* __restrict__ rowptr,
                         int* __restrict__ woff, int n) {
    __shared__ int warpsum[32];
    int tid = threadIdx.x, lane = tid & 31, wid = tid >> 5;
    const int CHUNK = (n + 1023) >> 10;
    int b = tid * CHUNK;
    int e = b + CHUNK; if (e > n) e = n;
    int s = 0;
    for (int i = b; i < e; ++i) s += cnt[i];
    int x = s;
#pragma unroll
    for (int o = 1; o < 32; o <<= 1) {
        int y = __shfl_up_sync(0xffffffffu, x, o);
        if (lane >= o) x += y;
    }
    if (lane == 31) warpsum[wid] = x;
    __syncthreads();
    if (wid == 0) {
        int w = warpsum[lane];
#pragma unroll
        for (int o = 1; o < 32; o <<= 1) {
            int y = __shfl_up_sync(0xffffffffu, w, o);
            if (lane >= o) w += y;
        }
        warpsum[lane] = w;
    }
    __syncthreads();
    int run = x - s + (wid > 0 ? warpsum[wid - 1] : 0);
    for (int i = b; i < e; ++i) {
        rowptr[i] = run; woff[i] = run;
        run += cnt[i];
    }
    if (tid == 1023) rowptr[n] = run;
}
__global__ void csr_scatter(const int* __restrict__ src, const int* __restrict__ dst,
                            int* __restrict__ woff, int* __restrict__ csrc, int E) {
    int e = blockIdx.x * blockDim.x + threadIdx.x;
    if (e < E) {
        int d = dst[e];
        int p = atomicAdd(&woff[d], 1);
        csrc[p] = src[e];
    }
}

// ---------------- tensor-core GEMM + fused attention epilogue -----------------
__device__ __forceinline__ void ldmA4(unsigned& a0, unsigned& a1, unsigned& a2, unsigned& a3,
                                      unsigned addr) {
    asm volatile("ldmatrix.sync.aligned.m8n8.x4.shared.b16 {%0,%1,%2,%3}, [%4];"
                 : "=r"(a0), "=r"(a1), "=r"(a2), "=r"(a3) : "r"(addr));
}
__device__ __forceinline__ void ldmB2t(unsigned& b0, unsigned& b1, unsigned addr) {
    asm volatile("ldmatrix.sync.aligned.m8n8.x2.trans.shared.b16 {%0,%1}, [%2];"
                 : "=r"(b0), "=r"(b1) : "r"(addr));
}
__device__ __forceinline__ void mma16816(float* d, unsigned a0, unsigned a1, unsigned a2,
                                         unsigned a3, unsigned b0, unsigned b1) {
    asm volatile("mma.sync.aligned.m16n8k16.row.col.f32.f16.f16.f32 "
                 "{%0,%1,%2,%3}, {%4,%5,%6,%7}, {%8,%9}, {%0,%1,%2,%3};"
                 : "+f"(d[0]), "+f"(d[1]), "+f"(d[2]), "+f"(d[3])
                 : "r"(a0), "r"(a1), "r"(a2), "r"(a3), "r"(b0), "r"(b1));
}

template <int OUT>
__global__ void gemm_mma_fused(const float* __restrict__ X, const float* __restrict__ Wg,
                               const float* __restrict__ As, const float* __restrict__ Ad,
                               __half* __restrict__ Hh, float* __restrict__ as_,
                               float* __restrict__ ad_, int n) {
    const int NH = OUT / 64;
    const int SA = 136;                 // A smem stride (halfs)
    const int SB = 72;                  // B smem stride (halfs)
    __shared__ __half hA[64 * SA];
    __shared__ __half hB[128 * SB];
    const int tid = threadIdx.x;
    const int warp = tid >> 5, lane = tid & 31;
    const int rowBase = blockIdx.x * 64, colBase = blockIdx.y * 64;
    const int head = blockIdx.y;

    // load A 64x128 fp32->fp16 (zero-fill OOB rows)
    for (int idx = tid; idx < 64 * 32; idx += 128) {
        int r = idx >> 5, c4 = idx & 31;
        int row = rowBase + r;
        float4 v = make_float4(0.f, 0.f, 0.f, 0.f);
        if (row < n) v = *(const float4*)&X[(size_t)row * 128 + c4 * 4];
        __half2 p0 = __floats2half2_rn(v.x, v.y);
        __half2 p1 = __floats2half2_rn(v.z, v.w);
        *(__half2*)&hA[r * SA + c4 * 4] = p0;
        *(__half2*)&hA[r * SA + c4 * 4 + 2] = p1;
    }
    // load B 128x64 fp32->fp16
    for (int idx = tid; idx < 128 * 16; idx += 128) {
        int k = idx >> 4, c4 = idx & 15;
        float4 v = *(const float4*)&Wg[(size_t)k * OUT + colBase + c4 * 4];
        __half2 p0 = __floats2half2_rn(v.x, v.y);
        __half2 p1 = __floats2half2_rn(v.z, v.w);
        *(__half2*)&hB[k * SB + c4 * 4] = p0;
        *(__half2*)&hB[k * SB + c4 * 4 + 2] = p1;
    }
    __syncthreads();

    unsigned baseA = (unsigned)__cvta_generic_to_shared(hA);
    unsigned baseB = (unsigned)__cvta_generic_to_shared(hB);
    float acc[8][4] = {};
    int aRow = warp * 16 + (lane & 15);
    int aKoff = (lane >> 4) * 8;
    int bRow = (lane & 15);

#pragma unroll
    for (int kt = 0; kt < 8; ++kt) {
        unsigned a0, a1, a2, a3;
        ldmA4(a0, a1, a2, a3, baseA + (aRow * SA + kt * 16 + aKoff) * 2);
#pragma unroll
        for (int j = 0; j < 8; ++j) {
            unsigned b0, b1;
            ldmB2t(b0, b1, baseB + ((kt * 16 + bRow) * SB + j * 8) * 2);
            mma16816(acc[j], a0, a1, a2, a3, b0, b1);
        }
    }

    // epilogue
    int g = lane >> 2, q = lane & 3;
    int r0 = rowBase + warp * 16 + g;
    int r1 = r0 + 8;
    float ps0 = 0.f, pd0 = 0.f, ps1 = 0.f, pd1 = 0.f;
#pragma unroll
    for (int j = 0; j < 8; ++j) {
        int c = j * 8 + q * 2;
        float s0 = __ldg(&As[head * 64 + c]), s1 = __ldg(&As[head * 64 + c + 1]);
        float d0 = __ldg(&Ad[head * 64 + c]), d1 = __ldg(&Ad[head * 64 + c + 1]);
        ps0 += acc[j][0] * s0 + acc[j][1] * s1;
        pd0 += acc[j][0] * d0 + acc[j][1] * d1;
        ps1 += acc[j][2] * s0 + acc[j][3] * s1;
        pd1 += acc[j][2] * d0 + acc[j][3] * d1;
    }
#pragma unroll
    for (int o = 1; o < 4; o <<= 1) {
        ps0 += __shfl_xor_sync(0xffffffffu, ps0, o);
        pd0 += __shfl_xor_sync(0xffffffffu, pd0, o);
        ps1 += __shfl_xor_sync(0xffffffffu, ps1, o);
        pd1 += __shfl_xor_sync(0xffffffffu, pd1, o);
    }
    if (q == 0) {
        if (r0 < n) { as_[r0 * NH + head] = ps0; ad_[r0 * NH + head] = pd0; }
        if (r1 < n) { as_[r1 * NH + head] = ps1; ad_[r1 * NH + head] = pd1; }
    }
#pragma unroll
    for (int j = 0; j < 8; ++j) {
        int c = colBase + j * 8 + q * 2;
        if (r0 < n) {
            __half2 p = __floats2half2_rn(acc[j][0], acc[j][1]);
            *(__half2*)&Hh[(size_t)r0 * OUT + c] = p;
        }
        if (r1 < n) {
            __half2 p = __floats2half2_rn(acc[j][2], acc[j][3]);
            *(__half2*)&Hh[(size_t)r1 * OUT + c] = p;
        }
    }
}

// ---------------- fused GAT softmax-aggregate (fp16 gather) -------------------
__global__ void gat_h2(const int* __restrict__ rowptr, const int* __restrict__ csrc,
                       const float* __restrict__ as_, const float* __restrict__ ad_,
                       const __half* __restrict__ hh, const float* __restrict__ bias,
                       float* __restrict__ out, int n) {
    int d = (blockIdx.x * blockDim.x + threadIdx.x) >> 5;
    if (d >= n) return;
    int lane = threadIdx.x & 31;
    int half = lane >> 4, li = lane & 15;
    int begin = rowptr[d], end = rowptr[d + 1];
    float ad_h = __ldg(&ad_[d * 2 + half]);
    float w0 = __expf(lrelu02(__ldg(&as_[d * 2 + half]) + ad_h));
    uint2 hu = *(const uint2*)&hh[(size_t)d * 128 + lane * 4];
    float2 h0 = __half22float2(*(__half2*)&hu.x);
    float2 h1 = __half22float2(*(__half2*)&hu.y);
    float4 acc = make_float4(w0 * h0.x, w0 * h0.y, w0 * h1.x, w0 * h1.y);
    float den = (li == 0) ? w0 : 0.f;
    int i = begin;
    for (; i + 1 < end; i += 2) {
        int sA = __ldg(&csrc[i]);
        int sB = __ldg(&csrc[i + 1]);
        float eA = __ldg(&as_[sA * 2 + half]);
        float eB = __ldg(&as_[sB * 2 + half]);
        uint2 uA = *(const uint2*)&hh[(size_t)sA * 128 + lane * 4];
        uint2 uB = *(const uint2*)&hh[(size_t)sB * 128 + lane * 4];
        float wA = __expf(lrelu02(eA + ad_h));
        float wB = __expf(lrelu02(eB + ad_h));
        float2 a0 = __half22float2(*(__half2*)&uA.x);
        float2 a1 = __half22float2(*(__half2*)&uA.y);
        float2 b0 = __half22float2(*(__half2*)&uB.x);
        float2 b1 = __half22float2(*(__half2*)&uB.y);
        acc.x = fmaf(wA, a0.x, acc.x); acc.y = fmaf(wA, a0.y, acc.y);
        acc.z = fmaf(wA, a1.x, acc.z); acc.w = fmaf(wA, a1.y, acc.w);
        acc.x = fmaf(wB, b0.x, acc.x); acc.y = fmaf(wB, b0.y, acc.y);
        acc.z = fmaf(wB, b1.x, acc.z); acc.w = fmaf(wB, b1.y, acc.w);
        if (li == 0) den += wA + wB;
    }
    if (i < end) {
        int s = __ldg(&csrc[i]);
        float es = __ldg(&as_[s * 2 + half]);
        uint2 u = *(const uint2*)&hh[(size_t)s * 128 + lane * 4];
        float w = __expf(lrelu02(es + ad_h));
        float2 a0 = __half22float2(*(__half2*)&u.x);
        float2 a1 = __half22float2(*(__half2*)&u.y);
        acc.x = fmaf(w, a0.x, acc.x); acc.y = fmaf(w, a0.y, acc.y);
        acc.z = fmaf(w, a1.x, acc.z); acc.w = fmaf(w, a1.y, acc.w);
        if (li == 0) den += w;
    }
    float den_b = __shfl_sync(0xffffffffu, den, half << 4) + 1e-16f;
    float rinv = 1.f / den_b;
    float4 bq = *(const float4*)&bias[lane * 4];
    float4 o;
    o.x = acc.x * rinv + bq.x; o.y = acc.y * rinv + bq.y;
    o.z = acc.z * rinv + bq.z; o.w = acc.w * rinv + bq.w;
    o.x = o.x > 0.f ? o.x : expm1f(o.x);
    o.y = o.y > 0.f ? o.y : expm1f(o.y);
    o.z = o.z > 0.f ? o.z : expm1f(o.z);
    o.w = o.w > 0.f ? o.w : expm1f(o.w);
    *(float4*)&out[(size_t)d * 128 + lane * 4] = o;
}

__global__ void gat_h1(const int* __restrict__ rowptr, const int* __restrict__ csrc,
                       const float* __restrict__ as_, const float* __restrict__ ad_,
                       const __half* __restrict__ hh, const float* __restrict__ bias,
                       float* __restrict__ out, int n) {
    int d = (blockIdx.x * blockDim.x + threadIdx.x) >> 5;
    if (d >= n) return;
    int lane = threadIdx.x & 31;
    int begin = rowptr[d], end = rowptr[d + 1];
    float ad_d = __ldg(&ad_[d]);
    float w0 = __expf(lrelu02(__ldg(&as_[d]) + ad_d));
    float2 hv = __half22float2(*(const __half2*)&hh[(size_t)d * 64 + lane * 2]);
    float2 acc = make_float2(w0 * hv.x, w0 * hv.y);
    float den = (lane == 0) ? w0 : 0.f;
    int i = begin;
    for (; i + 1 < end; i += 2) {
        int sA = __ldg(&csrc[i]);
        int sB = __ldg(&csrc[i + 1]);
        float eA = __ldg(&as_[sA]);
        float eB = __ldg(&as_[sB]);
        float2 vA = __half22float2(*(const __half2*)&hh[(size_t)sA * 64 + lane * 2]);
        float2 vB = __half22float2(*(const __half2*)&hh[(size_t)sB * 64 + lane * 2]);
        float wA = __expf(lrelu02(eA + ad_d));
        float wB = __expf(lrelu02(eB + ad_d));
        acc.x = fmaf(wA, vA.x, acc.x); acc.y = fmaf(wA, vA.y, acc.y);
        acc.x = fmaf(wB, vB.x, acc.x); acc.y = fmaf(wB, vB.y, acc.y);
        if (lane == 0) den += wA + wB;
    }
    if (i < end) {
        int s = __ldg(&csrc[i]);
        float es = __ldg(&as_[s]);
        float2 v = __half22float2(*(const __half2*)&hh[(size_t)s * 64 + lane * 2]);
        float w = __expf(lrelu02(es + ad_d));
        acc.x = fmaf(w, v.x, acc.x);
        acc.y = fmaf(w, v.y, acc.y);
        if (lane == 0) den += w;
    }
    float den_b = __shfl_sync(0xffffffffu, den, 0) + 1e-16f;
    float rinv = 1.f / den_b;
    float2 bq = *(const float2*)&bias[lane * 2];
    float2 o;
    o.x = acc.x * rinv + bq.x; o.y = acc.y * rinv + bq.y;
    o.x = o.x > 0.f ? o.x : expm1f(o.x);
    o.y = o.y > 0.f ? o.y : expm1f(o.y);
    *(float2*)&out[(size_t)d * 64 + lane * 2] = o;
}

// ---------------- final linear + sigmoid -------------------------------------
__global__ void final_lin(const float* __restrict__ H2, const float* __restrict__ Lw,
                          const float* __restrict__ Lb, float* __restrict__ out, int n) {
    __shared__ float sw[64 * 16];
    __shared__ float sb[16];
    int tid = threadIdx.x;
    for (int idx = tid; idx < 64 * 16; idx += 256) sw[idx] = Lw[idx];
    if (tid < 16) sb[tid] = Lb[tid];
    __syncthreads();
    int gw = (blockIdx.x * 256 + tid) >> 5;
    int nw = (gridDim.x * 256) >> 5;
    int lane = tid & 31;
    int o = lane & 15, half = lane >> 4;
    for (int i = gw; i < n; i += nw) {
        const float* row = &H2[(size_t)i * 64 + half * 32];
        float acc = 0.f;
#pragma unroll
        for (int c = 0; c < 32; ++c) acc = fmaf(row[c], sw[(half * 32 + c) * 16 + o], acc);
        acc += __shfl_xor_sync(0xffffffffu, acc, 16);
        if (lane < 16) out[(size_t)i * 16 + o] = 1.f / (1.f + __expf(-(acc + sb[o])));
    }
}

// ---------------- launcher ---------------------------------------------------
static inline int cdiv(long long a, long long b) { return (int)((a + b - 1) / b); }

extern "C" void kernel_launch(void* const* d_in, const int* in_sizes, int n_in,
                              void* d_out, int out_size) {
    const float* x   = (const float*)d_in[0];
    const int*   ei  = (const int*)d_in[1];
    const float* W1  = (const float*)d_in[2];
    const float* As1 = (const float*)d_in[3];
    const float* Ad1 = (const float*)d_in[4];
    const float* b1  = (const float*)d_in[5];
    const float* W2  = (const float*)d_in[6];
    const float* As2 = (const float*)d_in[7];
    const float* Ad2 = (const float*)d_in[8];
    const float* b2  = (const float*)d_in[9];
    const float* lw  = (const float*)d_in[10];
    const float* lb  = (const float*)d_in[11];
    float*       out = (float*)d_out;

    int n = in_sizes[0] / 128;
    int E = in_sizes[1] / 2;
    const int* src = ei;
    const int* dst = ei + E;

    __half *h1h, *h2h;
    float *as1, *ad1, *x2, *as2, *ad2, *o2;
    int *cnt, *rowptr, *woff, *csrc;
    cudaGetSymbolAddress((void**)&h1h, g_h1h);
    cudaGetSymbolAddress((void**)&as1, g_as1); cudaGetSymbolAddress((void**)&ad1, g_ad1);
    cudaGetSymbolAddress((void**)&x2, g_x2);
    cudaGetSymbolAddress((void**)&h2h, g_h2h);
    cudaGetSymbolAddress((void**)&as2, g_as2); cudaGetSymbolAddress((void**)&ad2, g_ad2);
    cudaGetSymbolAddress((void**)&o2, g_o2);
    cudaGetSymbolAddress((void**)&cnt, g_cnt); cudaGetSymbolAddress((void**)&rowptr, g_rowptr);
    cudaGetSymbolAddress((void**)&woff, g_woff); cudaGetSymbolAddress((void**)&csrc, g_csrc);

    const int T = 256;

    // ---- CSR build (shared by both layers) ----
    cudaMemsetAsync(cnt, 0, (size_t)n * sizeof(int));
    hist_dst<<<cdiv(E, T), T>>>(dst, cnt, E);
    scan_cnt<<<1, 1024>>>(cnt, rowptr, woff, n);
    csr_scatter<<<cdiv(E, T), T>>>(src, dst, woff, csrc, E);

    // ---- layer 1 (H=2, C=64, concat) ----
    gemm_mma_fused<128><<<dim3(cdiv(n, 64), 2), 128>>>(x, W1, As1, Ad1, h1h, as1, ad1, n);
    gat_h2<<<cdiv((long long)n * 32, T), T>>>(rowptr, csrc, as1, ad1, h1h, b1, x2, n);

    // ---- layer 2 (H=1, C=64) ----
    gemm_mma_fused<64><<<dim3(cdiv(n, 64), 1), 128>>>(x2, W2, As2, Ad2, h2h, as2, ad2, n);
    gat_h1<<<cdiv((long long)n * 32, T), T>>>(rowptr, csrc, as2, ad2, h2h, b2, o2, n);

    // ---- final linear + sigmoid ----
    final_lin<<<cdiv((long long)n * 32, T), T>>>(o2, lw, lb, out, n);
}